// round 1
// baseline (speedup 1.0000x reference)
#include <cuda_runtime.h>
#include <math.h>

// ---------------------------------------------------------------------------
// Problem constants
// ---------------------------------------------------------------------------
#define H_SP 50
#define W_SP 75
#define N_SP (H_SP * W_SP)   // 3750 spatial positions
#define R_ROIS 1000
#define C_MID 490            // 10 * 7 * 7
#define FC1_DIM 2048
#define LOC_DIM 324
#define SCORE_DIM 81

// ---------------------------------------------------------------------------
// Scratch (device globals: allocation-free rule)
// ---------------------------------------------------------------------------
__device__ float g_y1col[256 * N_SP];
__device__ float g_y1row[256 * N_SP];
__device__ float g_hcol [C_MID * N_SP];
__device__ float g_h    [C_MID * N_SP];
__device__ float g_flat [R_ROIS * C_MID];
__device__ float g_fc1  [R_ROIS * FC1_DIM];

// ---------------------------------------------------------------------------
// Implicit-GEMM conv for 15x1 (MODE=0, shift along h -> offset = d*75) and
// 1x15 (MODE=1, shift along w -> offset = d, bounded by row).
// X: [IC, 3750], Wt: [OC, IC, 15], Y: [OC, 3750]
// FUSE: Y = relu(acc + bias + P)   (second-branch epilogue)
// Tile: 64(M) x 64(N) x 16(K), 256 threads, 4x4 per thread.
// ---------------------------------------------------------------------------
template<int MODE, bool FUSE>
__global__ __launch_bounds__(256) void conv_kernel(
    const float* __restrict__ X, const float* __restrict__ Wt,
    const float* __restrict__ bias, const float* __restrict__ P,
    float* __restrict__ Y, int OC, int IC)
{
    __shared__ float As[16][64];
    __shared__ float Bs[16][64];

    const int nBase  = blockIdx.x * 64;
    const int ocBase = blockIdx.y * 64;
    const int t  = threadIdx.x;
    const int tx = t & 15;
    const int ty = t >> 4;

    // A-load mapping: each thread loads 4 consecutive k for one m-row
    const int am = t >> 2;            // 0..63
    const int ak = (t & 3) * 4;       // 0,4,8,12
    // B-load mapping: each thread loads 4 consecutive n for one k-row
    const int bk = t >> 4;            // 0..15
    const int bj = (t & 15) * 4;      // 0..60

    float acc[4][4];
#pragma unroll
    for (int i = 0; i < 4; ++i)
#pragma unroll
        for (int j = 0; j < 4; ++j) acc[i][j] = 0.f;

    int wj[4];
#pragma unroll
    for (int i = 0; i < 4; ++i) wj[i] = (nBase + bj + i) % W_SP;

    const bool arow_ok = (ocBase + am) < OC;
    const float* wrow = Wt + (size_t)(ocBase + am) * IC * 15;

    for (int tap = 0; tap < 15; ++tap) {
        const int d   = tap - 7;
        const int off = (MODE == 0) ? d * W_SP : d;

        bool bval[4];
#pragma unroll
        for (int i = 0; i < 4; ++i) {
            const int nn = nBase + bj + i + off;
            bool ok = (nn >= 0) && (nn < N_SP);
            if (MODE == 1) {
                const int w2 = wj[i] + d;
                ok = ok && (w2 >= 0) && (w2 < W_SP);
            }
            bval[i] = ok;
        }

        for (int ic0 = 0; ic0 < IC; ic0 += 16) {
            // stage A (weights)
#pragma unroll
            for (int i = 0; i < 4; ++i) {
                float v = 0.f;
                if (arow_ok) v = wrow[(size_t)(ic0 + ak + i) * 15 + tap];
                As[ak + i][am] = v;
            }
            // stage B (shifted activations)
            const float* Xr = X + (size_t)(ic0 + bk) * N_SP + nBase + bj + off;
#pragma unroll
            for (int i = 0; i < 4; ++i)
                Bs[bk][bj + i] = bval[i] ? Xr[i] : 0.f;
            __syncthreads();

#pragma unroll
            for (int k = 0; k < 16; ++k) {
                const float4 a4 = *(const float4*)&As[k][ty * 4];
                const float4 b4 = *(const float4*)&Bs[k][tx * 4];
                const float ar[4] = {a4.x, a4.y, a4.z, a4.w};
                const float br[4] = {b4.x, b4.y, b4.z, b4.w};
#pragma unroll
                for (int i = 0; i < 4; ++i)
#pragma unroll
                    for (int j = 0; j < 4; ++j)
                        acc[i][j] = fmaf(ar[i], br[j], acc[i][j]);
            }
            __syncthreads();
        }
    }

#pragma unroll
    for (int i = 0; i < 4; ++i) {
        const int m = ocBase + ty * 4 + i;
        if (m >= OC) continue;
        const float bv = bias[m];
#pragma unroll
        for (int j = 0; j < 4; ++j) {
            const int n = nBase + tx * 4 + j;
            if (n >= N_SP) continue;
            float v = acc[i][j] + bv;
            if (FUSE) v = fmaxf(v + P[(size_t)m * N_SP + n], 0.f);
            Y[(size_t)m * N_SP + n] = v;
        }
    }
}

// ---------------------------------------------------------------------------
// PSROI align with max pooling. One thread per (roi, channel) output.
// feat: [490, 3750] relu'd feature map; rois: [1000, 4]; out: [1000, 490]
// channel c = d*49 + gh*7 + gw  (same layout as the reshape in reference)
// ---------------------------------------------------------------------------
__global__ void psroi_kernel(const float* __restrict__ feat,
                             const float* __restrict__ rois,
                             float* __restrict__ out)
{
    const int idx = blockIdx.x * blockDim.x + threadIdx.x;
    if (idx >= R_ROIS * C_MID) return;
    const int r  = idx / C_MID;
    const int c  = idx % C_MID;
    const int gw = c % 7;
    const int gh = (c / 7) % 7;

    const float x1 = rois[r * 4 + 0] * 0.0625f;
    const float y1 = rois[r * 4 + 1] * 0.0625f;
    const float x2 = rois[r * 4 + 2] * 0.0625f;
    const float y2 = rois[r * 4 + 3] * 0.0625f;
    const float bw = (x2 - x1) * (1.f / 7.f);
    const float bh = (y2 - y1) * (1.f / 7.f);

    const float* plane = feat + (size_t)c * N_SP;
    float best = -1e30f;

#pragma unroll
    for (int sy = 0; sy < 2; ++sy) {
        float ys = y1 + ((float)gh + (sy + 0.5f) * 0.5f) * bh;
        ys = fminf(fmaxf(ys, 0.f), (float)(H_SP - 1));
        const float y0f = floorf(ys);
        const float ly  = ys - y0f;
        const int iy0 = (int)y0f;
        const int iy1 = min(iy0 + 1, H_SP - 1);
#pragma unroll
        for (int sx = 0; sx < 2; ++sx) {
            float xs = x1 + ((float)gw + (sx + 0.5f) * 0.5f) * bw;
            xs = fminf(fmaxf(xs, 0.f), (float)(W_SP - 1));
            const float x0f = floorf(xs);
            const float lx  = xs - x0f;
            const int ix0 = (int)x0f;
            const int ix1 = min(ix0 + 1, W_SP - 1);
            const float v00 = plane[iy0 * W_SP + ix0];
            const float v01 = plane[iy0 * W_SP + ix1];
            const float v10 = plane[iy1 * W_SP + ix0];
            const float v11 = plane[iy1 * W_SP + ix1];
            const float v = (1.f - ly) * ((1.f - lx) * v00 + lx * v01)
                          + ly        * ((1.f - lx) * v10 + lx * v11);
            best = fmaxf(best, v);
        }
    }
    out[idx] = best;
}

// ---------------------------------------------------------------------------
// Generic NT GEMM:  C[m, n] = (relu?)( bias[n] + sum_k A[m*K+k] * B[n*K+k] )
// A: [M, K] row-major, B: [N, K] row-major, C row stride = ldc.
// Tile 64x64x16, 256 threads, 4x4 per thread.
// ---------------------------------------------------------------------------
template<bool RELU>
__global__ __launch_bounds__(256) void gemm_nt(
    const float* __restrict__ A, const float* __restrict__ B,
    const float* __restrict__ bias, float* __restrict__ C,
    int M, int N, int K, int ldc)
{
    __shared__ float As[16][64];
    __shared__ float Bs[16][64];

    const int nBase = blockIdx.x * 64;
    const int mBase = blockIdx.y * 64;
    const int t  = threadIdx.x;
    const int tx = t & 15;
    const int ty = t >> 4;
    const int lr = t >> 2;        // row within tile 0..63
    const int lk = (t & 3) * 4;   // 0,4,8,12

    float acc[4][4];
#pragma unroll
    for (int i = 0; i < 4; ++i)
#pragma unroll
        for (int j = 0; j < 4; ++j) acc[i][j] = 0.f;

    const bool aok = (mBase + lr) < M;
    const bool bok = (nBase + lr) < N;
    const float* Arow = A + (size_t)(aok ? (mBase + lr) : 0) * K;
    const float* Brow = B + (size_t)(bok ? (nBase + lr) : 0) * K;

    for (int k0 = 0; k0 < K; k0 += 16) {
#pragma unroll
        for (int i = 0; i < 4; ++i) {
            const int kk = k0 + lk + i;
            const bool kin = kk < K;
            As[lk + i][lr] = (aok && kin) ? Arow[kk] : 0.f;
            Bs[lk + i][lr] = (bok && kin) ? Brow[kk] : 0.f;
        }
        __syncthreads();
#pragma unroll
        for (int k = 0; k < 16; ++k) {
            const float4 a4 = *(const float4*)&As[k][ty * 4];
            const float4 b4 = *(const float4*)&Bs[k][tx * 4];
            const float ar[4] = {a4.x, a4.y, a4.z, a4.w};
            const float br[4] = {b4.x, b4.y, b4.z, b4.w};
#pragma unroll
            for (int i = 0; i < 4; ++i)
#pragma unroll
                for (int j = 0; j < 4; ++j)
                    acc[i][j] = fmaf(ar[i], br[j], acc[i][j]);
        }
        __syncthreads();
    }

#pragma unroll
    for (int i = 0; i < 4; ++i) {
        const int m = mBase + ty * 4 + i;
        if (m >= M) continue;
#pragma unroll
        for (int j = 0; j < 4; ++j) {
            const int n = nBase + tx * 4 + j;
            if (n >= N) continue;
            float v = acc[i][j] + bias[n];
            if (RELU) v = fmaxf(v, 0.f);
            C[(size_t)m * ldc + n] = v;
        }
    }
}

// ---------------------------------------------------------------------------
// Launch
// ---------------------------------------------------------------------------
extern "C" void kernel_launch(void* const* d_in, const int* in_sizes, int n_in,
                              void* d_out, int out_size)
{
    const float* x         = (const float*)d_in[0];
    const float* rois      = (const float*)d_in[1];
    const float* w_col_max = (const float*)d_in[2];
    const float* b_col_max = (const float*)d_in[3];
    const float* w_col     = (const float*)d_in[4];
    const float* b_col     = (const float*)d_in[5];
    const float* w_row_max = (const float*)d_in[6];
    const float* b_row_max = (const float*)d_in[7];
    const float* w_row     = (const float*)d_in[8];
    const float* b_row     = (const float*)d_in[9];
    const float* fc1_w     = (const float*)d_in[10];
    const float* fc1_b     = (const float*)d_in[11];
    const float* score_w   = (const float*)d_in[12];
    const float* score_b   = (const float*)d_in[13];
    const float* loc_w     = (const float*)d_in[14];
    const float* loc_b     = (const float*)d_in[15];
    float* out = (float*)d_out;

    float *y1col, *y1row, *hcol, *h, *flat, *fc1;
    cudaGetSymbolAddress((void**)&y1col, g_y1col);
    cudaGetSymbolAddress((void**)&y1row, g_y1row);
    cudaGetSymbolAddress((void**)&hcol,  g_hcol);
    cudaGetSymbolAddress((void**)&h,     g_h);
    cudaGetSymbolAddress((void**)&flat,  g_flat);
    cudaGetSymbolAddress((void**)&fc1,   g_fc1);

    const int nTiles = (N_SP + 63) / 64;  // 59

    // Branch 1a: x --(15x1)--> y1col ; Branch 2a: x --(1x15)--> y1row
    dim3 g1(nTiles, 4);  // 256 output channels
    conv_kernel<0, false><<<g1, 256>>>(x, w_col_max, b_col_max, nullptr, y1col, 256, 2048);
    conv_kernel<1, false><<<g1, 256>>>(x, w_row_max, b_row_max, nullptr, y1row, 256, 2048);

    // Branch 1b: y1col --(1x15)--> hcol ; Branch 2b fused: relu(hcol + conv(y1row)) -> h
    dim3 g2(nTiles, (C_MID + 63) / 64);  // 59 x 8
    conv_kernel<1, false><<<g2, 256>>>(y1col, w_col, b_col, nullptr, hcol, C_MID, 256);
    conv_kernel<0, true ><<<g2, 256>>>(y1row, w_row, b_row, hcol,    h,    C_MID, 256);

    // PSROI align max -> flat [1000, 490]
    psroi_kernel<<<(R_ROIS * C_MID + 255) / 256, 256>>>(h, rois, flat);

    // fc1 = relu(flat @ fc1_w^T + b) -> [1000, 2048]
    gemm_nt<true ><<<dim3(FC1_DIM / 64, (R_ROIS + 63) / 64), 256>>>(
        flat, fc1_w, fc1_b, fc1, R_ROIS, FC1_DIM, C_MID, FC1_DIM);

    // heads: locs first (out[0:324000]), then scores (out[324000:405000])
    gemm_nt<false><<<dim3((LOC_DIM + 63) / 64, (R_ROIS + 63) / 64), 256>>>(
        fc1, loc_w, loc_b, out, R_ROIS, LOC_DIM, FC1_DIM, LOC_DIM);
    gemm_nt<false><<<dim3((SCORE_DIM + 63) / 64, (R_ROIS + 63) / 64), 256>>>(
        fc1, score_w, score_b, out + (size_t)R_ROIS * LOC_DIM,
        R_ROIS, SCORE_DIM, FC1_DIM, SCORE_DIM);
}

// round 2
// speedup vs baseline: 1.4459x; 1.4459x over previous
#include <cuda_runtime.h>
#include <math.h>

// ---------------------------------------------------------------------------
// Problem constants
// ---------------------------------------------------------------------------
#define H_SP 50
#define W_SP 75
#define N_SP 3750
#define R_ROIS 1000
#define C_MID 490
#define FC1_DIM 2048
#define LOC_DIM 324
#define SCORE_DIM 81

#define K1 30720          // conv1 GEMM K per branch (2048*15)
#define K2 7680           // conv2 GEMM K fused over both branches (2*15*256)

// ---------------------------------------------------------------------------
// Scratch (device globals: allocation-free rule). Zero-initialized at load.
// ---------------------------------------------------------------------------
__device__ float g_wt1[512 * K1];     // conv1 weights, [oc][tap*2048+ic]
__device__ float g_wt2[512 * K2];     // conv2 weights, [oc][b*3840+tap*256+ic] (rows 490..511 stay 0)
__device__ float g_Y1 [512 * N_SP];   // conv1 out: rows 0-255 col branch, 256-511 row branch
__device__ float g_h  [C_MID * N_SP]; // relu(conv2_col + conv2_row)
__device__ float g_flat[R_ROIS * C_MID];
__device__ float g_fc1 [R_ROIS * FC1_DIM];

// ---------------------------------------------------------------------------
// Weight transposes: [oc][ic][tap] -> K-contiguous [oc][tap][ic]
// ---------------------------------------------------------------------------
__global__ void transpose_w1(const float* __restrict__ wcm,
                             const float* __restrict__ wrm,
                             float* __restrict__ wt)
{
    __shared__ float tile[256 * 15];
    const int oc = blockIdx.x;               // 0..511
    const int t  = threadIdx.x;              // 256 threads
    const float* src = (oc < 256) ? (wcm + (size_t)oc * K1)
                                  : (wrm + (size_t)(oc - 256) * K1);
    float* dst = wt + (size_t)oc * K1;
    for (int ic0 = 0; ic0 < 2048; ic0 += 256) {
        for (int i = t; i < 256 * 15; i += 256) tile[i] = src[ic0 * 15 + i];
        __syncthreads();
        for (int j = t; j < 256 * 15; j += 256) {
            const int tap = j >> 8;
            const int ic  = j & 255;
            dst[tap * 2048 + ic0 + ic] = tile[ic * 15 + tap];
        }
        __syncthreads();
    }
}

__global__ void transpose_w2(const float* __restrict__ wcol,
                             const float* __restrict__ wrow,
                             float* __restrict__ wt)
{
    __shared__ float tile[256 * 15];
    const int oc = blockIdx.x;               // 0..489
    const int b  = blockIdx.y;               // 0: col (1x15), 1: row (15x1)
    const int t  = threadIdx.x;
    const float* src = (b == 0 ? wcol : wrow) + (size_t)oc * 3840;
    for (int i = t; i < 256 * 15; i += 256) tile[i] = src[i];
    __syncthreads();
    float* dst = wt + (size_t)oc * K2 + b * 3840;
    for (int j = t; j < 256 * 15; j += 256) {
        const int tap = j >> 8;
        const int ic  = j & 255;
        dst[tap * 256 + ic] = tile[ic * 15 + tap];
    }
}

// ---------------------------------------------------------------------------
// Fused implicit-GEMM conv. 64(M) x 128(N) x 16(K) tiles, 256 threads,
// 4x8 microtile, double-buffered smem with register-staged prefetch.
//
// CONV==1: A = g_wt1 [512][30720], X = x [2048][3750].
//          Block branch by mBase: <256 -> 15x1 (h-shift), else 1x15 (w-shift).
//          Out = acc + bias(branch). No relu.
// CONV==2: A = g_wt2 [512][7680], X = g_Y1 [512][3750].
//          k segment s=k>>8: b=s/15, tap=s%15; b=0 -> w-shift on rows 0-255,
//          b=1 -> h-shift on rows 256-511. Out = relu(acc + b0[m] + b1[m]).
// ---------------------------------------------------------------------------
template<int CONV>
__global__ __launch_bounds__(256) void conv_gemm(
    const float* __restrict__ A, const float* __restrict__ X,
    const float* __restrict__ bias0, const float* __restrict__ bias1,
    float* __restrict__ Y, int OC)
{
    constexpr int KTOT   = (CONV == 1) ? K1 : K2;
    constexpr int NSTEPS = KTOT / 16;

    __shared__ float As[2][16][68];   // stride 68: conflict-free STS, 16B-aligned rows
    __shared__ float Bs[2][16][128];

    const int t     = threadIdx.x;
    const int nBase = blockIdx.x * 128;
    const int mBase = blockIdx.y * 64;

    const int tx = t & 15;            // n-group (8 wide)
    const int ty = t >> 4;            // m-group (4 wide)

    // A global load: 1 float4 per thread per step
    const int am = t >> 2;            // 0..63
    const int ak = (t & 3) << 2;      // 0,4,8,12
    const float* Arow = A + (size_t)(mBase + am) * KTOT + ak;

    // B global load: 8 consecutive n per thread per step
    const int bk = t >> 4;            // 0..15 (k row)
    const int bc = (t & 15) << 3;     // 0..120 (n col base)
    const int nb = nBase + bc;
    const int w0 = nb % W_SP;

    const bool blk_mode0 = (CONV == 1) && (mBase < 256);

    float acc[4][8];
#pragma unroll
    for (int i = 0; i < 4; ++i)
#pragma unroll
        for (int j = 0; j < 8; ++j) acc[i][j] = 0.f;

    float4 aReg;
    float  bReg[8];

    auto ldgTile = [&](int s) {
        const int k0 = s * 16;
        aReg = *reinterpret_cast<const float4*>(Arow + k0);
        int tap, xrow;
        bool mode0;
        if (CONV == 1) {
            tap   = k0 >> 11;
            xrow  = (k0 & 2047) + bk;
            mode0 = blk_mode0;
        } else {
            const int seg = k0 >> 8;
            const int b   = (seg >= 15) ? 1 : 0;
            tap   = seg - b * 15;
            xrow  = b * 256 + (k0 & 255) + bk;
            mode0 = (b == 1);
        }
        const int d   = tap - 7;
        const int off = mode0 ? d * W_SP : d;
        const float* Xr = X + (size_t)xrow * N_SP;
#pragma unroll
        for (int i = 0; i < 8; ++i) {
            const int nn = nb + i + off;
            bool ok = ((unsigned)nn < N_SP);
            if (!mode0) {
                int wi = w0 + i; if (wi >= W_SP) wi -= W_SP;
                wi += d;
                ok = ok && ((unsigned)wi < W_SP);
            }
            bReg[i] = ok ? __ldg(Xr + nn) : 0.f;
        }
    };

    auto stsTile = [&](int buf) {
        As[buf][ak + 0][am] = aReg.x;
        As[buf][ak + 1][am] = aReg.y;
        As[buf][ak + 2][am] = aReg.z;
        As[buf][ak + 3][am] = aReg.w;
        float4* bp = reinterpret_cast<float4*>(&Bs[buf][bk][bc]);
        bp[0] = make_float4(bReg[0], bReg[1], bReg[2], bReg[3]);
        bp[1] = make_float4(bReg[4], bReg[5], bReg[6], bReg[7]);
    };

    auto compute = [&](int buf) {
#pragma unroll
        for (int k = 0; k < 16; ++k) {
            const float4 a4 = *reinterpret_cast<const float4*>(&As[buf][k][ty << 2]);
            const float4 b0 = *reinterpret_cast<const float4*>(&Bs[buf][k][bc]);
            const float4 b1 = *reinterpret_cast<const float4*>(&Bs[buf][k][bc + 4]);
            const float ar[4] = {a4.x, a4.y, a4.z, a4.w};
            const float br[8] = {b0.x, b0.y, b0.z, b0.w, b1.x, b1.y, b1.z, b1.w};
#pragma unroll
            for (int i = 0; i < 4; ++i)
#pragma unroll
                for (int j = 0; j < 8; ++j)
                    acc[i][j] = fmaf(ar[i], br[j], acc[i][j]);
        }
    };

    ldgTile(0);
    stsTile(0);
    __syncthreads();

    for (int s = 0; s < NSTEPS; ++s) {
        const int cur = s & 1;
        if (s + 1 < NSTEPS) ldgTile(s + 1);
        compute(cur);
        if (s + 1 < NSTEPS) {
            stsTile(cur ^ 1);
            __syncthreads();
        }
    }

    // Epilogue
#pragma unroll
    for (int i = 0; i < 4; ++i) {
        const int m = mBase + (ty << 2) + i;
        if (m >= OC) continue;
        float bv;
        if (CONV == 1) bv = (m < 256) ? bias0[m] : bias1[m - 256];
        else           bv = bias0[m] + bias1[m];
#pragma unroll
        for (int j = 0; j < 8; ++j) {
            const int n = nBase + bc + j;  // note: bc == tx*8
            if (n >= N_SP) continue;
            float v = acc[i][j] + bv;
            if (CONV == 2) v = fmaxf(v, 0.f);
            Y[(size_t)m * N_SP + n] = v;
        }
    }
}

// ---------------------------------------------------------------------------
// PSROI align max pooling: one thread per (roi, channel)
// ---------------------------------------------------------------------------
__global__ void psroi_kernel(const float* __restrict__ feat,
                             const float* __restrict__ rois,
                             float* __restrict__ out)
{
    const int idx = blockIdx.x * blockDim.x + threadIdx.x;
    if (idx >= R_ROIS * C_MID) return;
    const int r  = idx / C_MID;
    const int c  = idx % C_MID;
    const int gw = c % 7;
    const int gh = (c / 7) % 7;

    const float x1 = rois[r * 4 + 0] * 0.0625f;
    const float y1 = rois[r * 4 + 1] * 0.0625f;
    const float x2 = rois[r * 4 + 2] * 0.0625f;
    const float y2 = rois[r * 4 + 3] * 0.0625f;
    const float bw = (x2 - x1) * (1.f / 7.f);
    const float bh = (y2 - y1) * (1.f / 7.f);

    const float* plane = feat + (size_t)c * N_SP;
    float best = -1e30f;

#pragma unroll
    for (int sy = 0; sy < 2; ++sy) {
        float ys = y1 + ((float)gh + (sy + 0.5f) * 0.5f) * bh;
        ys = fminf(fmaxf(ys, 0.f), (float)(H_SP - 1));
        const float y0f = floorf(ys);
        const float ly  = ys - y0f;
        const int iy0 = (int)y0f;
        const int iy1 = min(iy0 + 1, H_SP - 1);
#pragma unroll
        for (int sx = 0; sx < 2; ++sx) {
            float xs = x1 + ((float)gw + (sx + 0.5f) * 0.5f) * bw;
            xs = fminf(fmaxf(xs, 0.f), (float)(W_SP - 1));
            const float x0f = floorf(xs);
            const float lx  = xs - x0f;
            const int ix0 = (int)x0f;
            const int ix1 = min(ix0 + 1, W_SP - 1);
            const float v00 = plane[iy0 * W_SP + ix0];
            const float v01 = plane[iy0 * W_SP + ix1];
            const float v10 = plane[iy1 * W_SP + ix0];
            const float v11 = plane[iy1 * W_SP + ix1];
            const float v = (1.f - ly) * ((1.f - lx) * v00 + lx * v01)
                          + ly        * ((1.f - lx) * v10 + lx * v11);
            best = fmaxf(best, v);
        }
    }
    out[idx] = best;
}

// ---------------------------------------------------------------------------
// Generic NT GEMM (FC layers): C[m,n] = (relu?)(bias[n] + sum_k A[m,k]*B[n,k])
// ---------------------------------------------------------------------------
template<bool RELU>
__global__ __launch_bounds__(256) void gemm_nt(
    const float* __restrict__ A, const float* __restrict__ B,
    const float* __restrict__ bias, float* __restrict__ C,
    int M, int N, int K, int ldc)
{
    __shared__ float As[16][64];
    __shared__ float Bs[16][64];

    const int nBase = blockIdx.x * 64;
    const int mBase = blockIdx.y * 64;
    const int t  = threadIdx.x;
    const int tx = t & 15;
    const int ty = t >> 4;
    const int lr = t >> 2;
    const int lk = (t & 3) * 4;

    float acc[4][4];
#pragma unroll
    for (int i = 0; i < 4; ++i)
#pragma unroll
        for (int j = 0; j < 4; ++j) acc[i][j] = 0.f;

    const bool aok = (mBase + lr) < M;
    const bool bok = (nBase + lr) < N;
    const float* Arow = A + (size_t)(aok ? (mBase + lr) : 0) * K;
    const float* Brow = B + (size_t)(bok ? (nBase + lr) : 0) * K;

    for (int k0 = 0; k0 < K; k0 += 16) {
#pragma unroll
        for (int i = 0; i < 4; ++i) {
            const int kk = k0 + lk + i;
            const bool kin = kk < K;
            As[lk + i][lr] = (aok && kin) ? Arow[kk] : 0.f;
            Bs[lk + i][lr] = (bok && kin) ? Brow[kk] : 0.f;
        }
        __syncthreads();
#pragma unroll
        for (int k = 0; k < 16; ++k) {
            const float4 a4 = *(const float4*)&As[k][ty * 4];
            const float4 b4 = *(const float4*)&Bs[k][tx * 4];
            const float ar[4] = {a4.x, a4.y, a4.z, a4.w};
            const float br[4] = {b4.x, b4.y, b4.z, b4.w};
#pragma unroll
            for (int i = 0; i < 4; ++i)
#pragma unroll
                for (int j = 0; j < 4; ++j)
                    acc[i][j] = fmaf(ar[i], br[j], acc[i][j]);
        }
        __syncthreads();
    }

#pragma unroll
    for (int i = 0; i < 4; ++i) {
        const int m = mBase + ty * 4 + i;
        if (m >= M) continue;
#pragma unroll
        for (int j = 0; j < 4; ++j) {
            const int n = nBase + tx * 4 + j;
            if (n >= N) continue;
            float v = acc[i][j] + bias[n];
            if (RELU) v = fmaxf(v, 0.f);
            C[(size_t)m * ldc + n] = v;
        }
    }
}

// ---------------------------------------------------------------------------
// Launch
// ---------------------------------------------------------------------------
extern "C" void kernel_launch(void* const* d_in, const int* in_sizes, int n_in,
                              void* d_out, int out_size)
{
    const float* x         = (const float*)d_in[0];
    const float* rois      = (const float*)d_in[1];
    const float* w_col_max = (const float*)d_in[2];
    const float* b_col_max = (const float*)d_in[3];
    const float* w_col     = (const float*)d_in[4];
    const float* b_col     = (const float*)d_in[5];
    const float* w_row_max = (const float*)d_in[6];
    const float* b_row_max = (const float*)d_in[7];
    const float* w_row     = (const float*)d_in[8];
    const float* b_row     = (const float*)d_in[9];
    const float* fc1_w     = (const float*)d_in[10];
    const float* fc1_b     = (const float*)d_in[11];
    const float* score_w   = (const float*)d_in[12];
    const float* score_b   = (const float*)d_in[13];
    const float* loc_w     = (const float*)d_in[14];
    const float* loc_b     = (const float*)d_in[15];
    float* out = (float*)d_out;

    float *wt1, *wt2, *Y1, *h, *flat, *fc1;
    cudaGetSymbolAddress((void**)&wt1,  g_wt1);
    cudaGetSymbolAddress((void**)&wt2,  g_wt2);
    cudaGetSymbolAddress((void**)&Y1,   g_Y1);
    cudaGetSymbolAddress((void**)&h,    g_h);
    cudaGetSymbolAddress((void**)&flat, g_flat);
    cudaGetSymbolAddress((void**)&fc1,  g_fc1);

    // Weight layout transform (K-contiguous for float4 A loads)
    transpose_w1<<<512, 256>>>(w_col_max, w_row_max, wt1);
    transpose_w2<<<dim3(490, 2), 256>>>(w_col, w_row, wt2);

    // Fused conv1 (both 2048->256 branches, M=512): 30 x 8 tiles = 240 blocks
    conv_gemm<1><<<dim3(30, 8), 256>>>(wt1, x, b_col_max, b_row_max, Y1, 512);

    // Fused conv2 (sum of both 256->490 branches + relu): 30 x 8 tiles
    conv_gemm<2><<<dim3(30, 8), 256>>>(wt2, Y1, b_col, b_row, h, C_MID);

    // PSROI align max -> flat [1000, 490]
    psroi_kernel<<<(R_ROIS * C_MID + 255) / 256, 256>>>(h, rois, flat);

    // fc1 = relu(flat @ fc1_w^T + b) -> [1000, 2048]
    gemm_nt<true ><<<dim3(FC1_DIM / 64, (R_ROIS + 63) / 64), 256>>>(
        flat, fc1_w, fc1_b, fc1, R_ROIS, FC1_DIM, C_MID, FC1_DIM);

    // heads
    gemm_nt<false><<<dim3((LOC_DIM + 63) / 64, (R_ROIS + 63) / 64), 256>>>(
        fc1, loc_w, loc_b, out, R_ROIS, LOC_DIM, FC1_DIM, LOC_DIM);
    gemm_nt<false><<<dim3((SCORE_DIM + 63) / 64, (R_ROIS + 63) / 64), 256>>>(
        fc1, score_w, score_b, out + (size_t)R_ROIS * LOC_DIM,
        R_ROIS, SCORE_DIM, FC1_DIM, SCORE_DIM);
}

// round 7
// speedup vs baseline: 3.8786x; 2.6825x over previous
#include <cuda_runtime.h>
#include <cuda_bf16.h>
#include <stdint.h>
#include <math.h>

// ---------------------------------------------------------------------------
// Problem constants
// ---------------------------------------------------------------------------
#define H_SP 50
#define W_SP 75
#define N_SP 3750
#define R_ROIS 1000
#define C_MID 490
#define FC1_DIM 2048
#define LOC_DIM 324
#define SCORE_DIM 81
#define K1 30720            // conv1 GEMM K (15 taps * 2048 ic)
#define K2 7680             // conv2 GEMM K (2 branches * 15 taps * 256 ic)
#define OC1 512

// smem staging: 4 arrays (Ahi, Alo, Bhi, Blo), 128 rows x 32 bf16, row pad 80B
#define ROWB  80
#define ARRB  (128 * ROWB)          // 10240
#define STAGE (4 * ARRB)            // 40960
#define DYN_SMEM (2 * STAGE)        // 81920 (double buffer)

// ---------------------------------------------------------------------------
// Scratch (device globals, zero-initialized at load)
// ---------------------------------------------------------------------------
__device__ __nv_bfloat16 g_w1hi[OC1 * K1], g_w1lo[OC1 * K1];
__device__ __nv_bfloat16 g_w2hi[OC1 * K2], g_w2lo[OC1 * K2];   // rows 490..511 stay 0
__device__ __nv_bfloat16 g_xthi[N_SP * 2048], g_xtlo[N_SP * 2048];
__device__ __nv_bfloat16 g_y1thi[N_SP * 512], g_y1tlo[N_SP * 512];
__device__ float g_hT  [N_SP * C_MID];
__device__ float g_flat[R_ROIS * C_MID];
__device__ float g_fc1 [R_ROIS * FC1_DIM];

// ---------------------------------------------------------------------------
// PTX helpers (all base-sm_100-safe: cp.async / ldmatrix / mma.sync)
// ---------------------------------------------------------------------------
__device__ __forceinline__ uint32_t smem_u32(const void* p) {
    uint32_t a;
    asm("{ .reg .u64 t; cvta.to.shared.u64 t, %1; cvt.u32.u64 %0, t; }"
        : "=r"(a) : "l"(p));
    return a;
}
__device__ __forceinline__ void cpa16(uint32_t dst, const void* src, uint32_t sz) {
    asm volatile("cp.async.ca.shared.global [%0], [%1], 16, %2;"
                 :: "r"(dst), "l"(src), "r"(sz));
}
#define CP_COMMIT() asm volatile("cp.async.commit_group;" ::: "memory")
#define CP_WAIT1()  asm volatile("cp.async.wait_group 1;" ::: "memory")
#define CP_WAIT0()  asm volatile("cp.async.wait_group 0;" ::: "memory")

#define LDM_X4(r, addr) \
    asm volatile("ldmatrix.sync.aligned.m8n8.x4.shared.b16 {%0,%1,%2,%3}, [%4];" \
        : "=r"((r)[0]), "=r"((r)[1]), "=r"((r)[2]), "=r"((r)[3]) : "r"(addr))

#define MMA_BF16(d, a, b) \
    asm volatile("mma.sync.aligned.m16n8k16.row.col.f32.bf16.bf16.f32 " \
        "{%0,%1,%2,%3}, {%4,%5,%6,%7}, {%8,%9}, {%0,%1,%2,%3};" \
        : "+f"((d)[0]), "+f"((d)[1]), "+f"((d)[2]), "+f"((d)[3]) \
        : "r"((a)[0]), "r"((a)[1]), "r"((a)[2]), "r"((a)[3]), "r"((b)[0]), "r"((b)[1]))

// ---------------------------------------------------------------------------
// Prep: conv1 weights [oc][2048][15] -> bf16 hi/lo K-major [oc][tap*2048+ic]
// ---------------------------------------------------------------------------
__global__ void prep_w1(const float* __restrict__ wcm, const float* __restrict__ wrm,
                        __nv_bfloat16* __restrict__ hi, __nv_bfloat16* __restrict__ lo)
{
    __shared__ float tile[256 * 15];
    const int oc = blockIdx.x;
    const int t  = threadIdx.x;
    const float* src = (oc < 256) ? (wcm + (size_t)oc * K1)
                                  : (wrm + (size_t)(oc - 256) * K1);
    for (int ic0 = 0; ic0 < 2048; ic0 += 256) {
        for (int i = t; i < 256 * 15; i += 256) tile[i] = src[ic0 * 15 + i];
        __syncthreads();
        for (int j = t; j < 256 * 15; j += 256) {
            const int tap = j >> 8;
            const int ic  = j & 255;
            const float v = tile[ic * 15 + tap];
            const __nv_bfloat16 h = __float2bfloat16(v);
            const size_t idx = (size_t)oc * K1 + tap * 2048 + ic0 + ic;
            hi[idx] = h;
            lo[idx] = __float2bfloat16(v - __bfloat162float(h));
        }
        __syncthreads();
    }
}

// conv2 weights [oc][256][15] -> bf16 hi/lo [oc][b*3840 + tap*256 + ic]
__global__ void prep_w2(const float* __restrict__ wcol, const float* __restrict__ wrow,
                        __nv_bfloat16* __restrict__ hi, __nv_bfloat16* __restrict__ lo)
{
    __shared__ float tile[256 * 15];
    const int oc = blockIdx.x;   // 0..489
    const int b  = blockIdx.y;   // 0: col (1x15), 1: row (15x1)
    const int t  = threadIdx.x;
    const float* src = (b == 0 ? wcol : wrow) + (size_t)oc * 3840;
    for (int i = t; i < 256 * 15; i += 256) tile[i] = src[i];
    __syncthreads();
    for (int j = t; j < 256 * 15; j += 256) {
        const int tap = j >> 8;
        const int ic  = j & 255;
        const float v = tile[ic * 15 + tap];
        const __nv_bfloat16 h = __float2bfloat16(v);
        const size_t idx = (size_t)oc * K2 + b * 3840 + tap * 256 + ic;
        hi[idx] = h;
        lo[idx] = __float2bfloat16(v - __bfloat162float(h));
    }
}

// x [2048][3750] -> XT hi/lo [3750][2048] bf16
__global__ void prep_xt(const float* __restrict__ x,
                        __nv_bfloat16* __restrict__ hi, __nv_bfloat16* __restrict__ lo)
{
    __shared__ float tile[32][33];
    const int bi = blockIdx.x;            // n tiles (118)
    const int bj = blockIdx.y;            // ic tiles (64)
    const int tx = threadIdx.x & 31;
    const int ty = threadIdx.x >> 5;      // 0..7
#pragma unroll
    for (int r = 0; r < 4; ++r) {
        const int ic = bj * 32 + ty + r * 8;
        const int n  = bi * 32 + tx;
        tile[ty + r * 8][tx] = (n < N_SP) ? x[(size_t)ic * N_SP + n] : 0.f;
    }
    __syncthreads();
#pragma unroll
    for (int r = 0; r < 4; ++r) {
        const int n  = bi * 32 + ty + r * 8;
        const int ic = bj * 32 + tx;
        if (n < N_SP) {
            const float v = tile[tx][ty + r * 8];
            const __nv_bfloat16 h = __float2bfloat16(v);
            hi[(size_t)n * 2048 + ic] = h;
            lo[(size_t)n * 2048 + ic] = __float2bfloat16(v - __bfloat162float(h));
        }
    }
}

// ---------------------------------------------------------------------------
// Implicit-conv GEMM on mma.sync (bf16, fp32 acc), 3-way hi/lo split.
// Block 128(M=oc) x 128(N=spatial), K chunks of 32, cp.async double buffer.
// 8 warps in 4x2 (m x n); warp tile 32x64 via m16n8k16.
//
// CONV==1: W = g_w1 [512][K1], X = XT [3750][2048]. mBase<256 -> h-shift.
//          Epilogue: Y1T hi/lo bf16 [n][512] = acc + bias.
// CONV==2: W = g_w2 [512][K2], X = Y1T [3750][512]. k-seg selects branch/shift.
//          Epilogue: hT fp32 [n][490] = relu(acc + b_col + b_row).
// ---------------------------------------------------------------------------
template<int CONV>
__global__ __launch_bounds__(256) void conv_mma(
    const __nv_bfloat16* __restrict__ Whi, const __nv_bfloat16* __restrict__ Wlo,
    const __nv_bfloat16* __restrict__ Xhi, const __nv_bfloat16* __restrict__ Xlo,
    const float* __restrict__ bias0, const float* __restrict__ bias1,
    __nv_bfloat16* __restrict__ y1thi, __nv_bfloat16* __restrict__ y1tlo,
    float* __restrict__ hT)
{
    constexpr int KTOT = (CONV == 1) ? K1 : K2;
    constexpr int NC   = KTOT / 32;
    constexpr int LDB  = (CONV == 1) ? 2048 : 512;

    extern __shared__ char smem[];
    const uint32_t sbase = smem_u32(smem);

    const int t    = threadIdx.x;
    const int wid  = t >> 5;
    const int lane = t & 31;
    const int wm   = wid >> 1;        // 0..3 (m)
    const int wn   = wid & 1;         // 0..1 (n)
    const int mBase = blockIdx.y * 128;
    const int nBase = blockIdx.x * 128;
    const bool mode0_c1 = (CONV == 1) && (mBase < 256);

    // staging rows: thread covers virtual rows t and t+256.
    // arr: 0=Ahi 1=Alo 2=Bhi 3=Blo; row 0..127 within array.
    int arrv[2], rowv[2], nrv[2], w0v[2];
#pragma unroll
    for (int h = 0; h < 2; ++h) {
        const int v = t + h * 256;
        arrv[h] = v >> 7;
        rowv[h] = v & 127;
        nrv[h]  = nBase + rowv[h];
        w0v[h]  = nrv[h] % W_SP;
    }

    float acc[2][8][4];
#pragma unroll
    for (int i = 0; i < 2; ++i)
#pragma unroll
        for (int j = 0; j < 8; ++j)
#pragma unroll
            for (int q = 0; q < 4; ++q) acc[i][j][q] = 0.f;

    auto stage = [&](int buf, int c) {
        const int k0 = c * 32;
        int d, coloff;
        bool mode0;
        if (CONV == 1) {
            const int tap = k0 >> 11;
            coloff = k0 & 2047;
            mode0  = mode0_c1;
            d = tap - 7;
        } else {
            const int br  = (k0 >= 3840) ? 1 : 0;
            const int rem = k0 - br * 3840;
            const int tap = rem >> 8;
            coloff = br * 256 + (rem & 255);
            mode0  = (br == 1);
            d = tap - 7;
        }
        const int off = mode0 ? d * W_SP : d;

#pragma unroll
        for (int h = 0; h < 2; ++h) {
            const int arr = arrv[h];
            const int row = rowv[h];
            const uint32_t dst = sbase + buf * STAGE + arr * ARRB + row * ROWB;
            const char* src;
            uint32_t sz = 16;
            if (arr == 0) {
                src = (const char*)(Whi + (size_t)(mBase + row) * KTOT + k0);
            } else if (arr == 1) {
                src = (const char*)(Wlo + (size_t)(mBase + row) * KTOT + k0);
            } else {
                const int nr = nrv[h];
                bool ok;
                if (mode0) ok = (nr < N_SP) && ((unsigned)(nr + off) < (unsigned)N_SP);
                else       ok = (nr < N_SP) && ((unsigned)(w0v[h] + d) < (unsigned)W_SP);
                const long ns = ok ? (long)nr + off : 0;
                src = (const char*)((arr == 2 ? Xhi : Xlo) + ns * (long)LDB + coloff);
                sz = ok ? 16u : 0u;
            }
#pragma unroll
            for (int j = 0; j < 4; ++j) cpa16(dst + j * 16, src + j * 16, sz);
        }
    };

    auto compute = [&](int buf) {
        const uint32_t sb = sbase + buf * STAGE;
        const int lr = lane & 15;
        const int lc = lane >> 4;
#pragma unroll
        for (int k16 = 0; k16 < 32; k16 += 16) {
            const uint32_t kb = (uint32_t)(k16 + lc * 8) * 2;
            uint32_t a_hi[2][4], a_lo[2][4];
#pragma unroll
            for (int im = 0; im < 2; ++im) {
                const uint32_t ad = sb + (uint32_t)(wm * 32 + im * 16 + lr) * ROWB + kb;
                LDM_X4(a_hi[im], ad);
                LDM_X4(a_lo[im], ad + ARRB);
            }
            uint32_t b_hi[8][2], b_lo[8][2];
#pragma unroll
            for (int ib = 0; ib < 4; ++ib) {
                const uint32_t bd = sb + 2 * ARRB
                                  + (uint32_t)(wn * 64 + ib * 16 + lr) * ROWB + kb;
                uint32_t r4[4];
                LDM_X4(r4, bd);
                b_hi[2 * ib][0] = r4[0]; b_hi[2 * ib][1] = r4[2];
                b_hi[2 * ib + 1][0] = r4[1]; b_hi[2 * ib + 1][1] = r4[3];
                LDM_X4(r4, bd + ARRB);
                b_lo[2 * ib][0] = r4[0]; b_lo[2 * ib][1] = r4[2];
                b_lo[2 * ib + 1][0] = r4[1]; b_lo[2 * ib + 1][1] = r4[3];
            }
#pragma unroll
            for (int im = 0; im < 2; ++im)
#pragma unroll
                for (int in = 0; in < 8; ++in) MMA_BF16(acc[im][in], a_hi[im], b_hi[in]);
#pragma unroll
            for (int im = 0; im < 2; ++im)
#pragma unroll
                for (int in = 0; in < 8; ++in) MMA_BF16(acc[im][in], a_hi[im], b_lo[in]);
#pragma unroll
            for (int im = 0; im < 2; ++im)
#pragma unroll
                for (int in = 0; in < 8; ++in) MMA_BF16(acc[im][in], a_lo[im], b_hi[in]);
        }
    };

    stage(0, 0);
    CP_COMMIT();
    for (int c = 0; c < NC; ++c) {
        if (c + 1 < NC) {
            stage((c + 1) & 1, c + 1);
            CP_COMMIT();
            CP_WAIT1();
        } else {
            CP_WAIT0();
        }
        __syncthreads();
        compute(c & 1);
        __syncthreads();
    }

    // epilogue: standard m16n8 D layout
    const int g  = lane >> 2;
    const int tq = lane & 3;
#pragma unroll
    for (int im = 0; im < 2; ++im) {
        const int mA = mBase + wm * 32 + im * 16 + g;
        const int mB = mA + 8;
        float bvA, bvB;
        if (CONV == 1) {
            bvA = (mA < 256) ? bias0[mA] : bias1[mA - 256];
            bvB = (mB < 256) ? bias0[mB] : bias1[mB - 256];
        } else {
            bvA = (mA < C_MID) ? bias0[mA] + bias1[mA] : 0.f;
            bvB = (mB < C_MID) ? bias0[mB] + bias1[mB] : 0.f;
        }
#pragma unroll
        for (int in = 0; in < 8; ++in) {
            const int n0 = nBase + wn * 64 + in * 8 + tq * 2;
            const int n1 = n0 + 1;
            const float* d = acc[im][in];
            if (CONV == 1) {
                if (n0 < N_SP) {
                    float vA = d[0] + bvA;
                    __nv_bfloat16 hA = __float2bfloat16(vA);
                    y1thi[(size_t)n0 * 512 + mA] = hA;
                    y1tlo[(size_t)n0 * 512 + mA] = __float2bfloat16(vA - __bfloat162float(hA));
                    float vB = d[2] + bvB;
                    __nv_bfloat16 hB = __float2bfloat16(vB);
                    y1thi[(size_t)n0 * 512 + mB] = hB;
                    y1tlo[(size_t)n0 * 512 + mB] = __float2bfloat16(vB - __bfloat162float(hB));
                }
                if (n1 < N_SP) {
                    float vA = d[1] + bvA;
                    __nv_bfloat16 hA = __float2bfloat16(vA);
                    y1thi[(size_t)n1 * 512 + mA] = hA;
                    y1tlo[(size_t)n1 * 512 + mA] = __float2bfloat16(vA - __bfloat162float(hA));
                    float vB = d[3] + bvB;
                    __nv_bfloat16 hB = __float2bfloat16(vB);
                    y1thi[(size_t)n1 * 512 + mB] = hB;
                    y1tlo[(size_t)n1 * 512 + mB] = __float2bfloat16(vB - __bfloat162float(hB));
                }
            } else {
                if (n0 < N_SP) {
                    if (mA < C_MID) hT[(size_t)n0 * C_MID + mA] = fmaxf(d[0] + bvA, 0.f);
                    if (mB < C_MID) hT[(size_t)n0 * C_MID + mB] = fmaxf(d[2] + bvB, 0.f);
                }
                if (n1 < N_SP) {
                    if (mA < C_MID) hT[(size_t)n1 * C_MID + mA] = fmaxf(d[1] + bvA, 0.f);
                    if (mB < C_MID) hT[(size_t)n1 * C_MID + mB] = fmaxf(d[3] + bvB, 0.f);
                }
            }
        }
    }
}

// ---------------------------------------------------------------------------
// PSROI align max pooling; reads transposed feature map hT [n][490]
// ---------------------------------------------------------------------------
__global__ void psroi_kernel(const float* __restrict__ hT,
                             const float* __restrict__ rois,
                             float* __restrict__ out)
{
    const int idx = blockIdx.x * blockDim.x + threadIdx.x;
    if (idx >= R_ROIS * C_MID) return;
    const int r  = idx / C_MID;
    const int c  = idx % C_MID;
    const int gw = c % 7;
    const int gh = (c / 7) % 7;

    const float x1 = rois[r * 4 + 0] * 0.0625f;
    const float y1 = rois[r * 4 + 1] * 0.0625f;
    const float x2 = rois[r * 4 + 2] * 0.0625f;
    const float y2 = rois[r * 4 + 3] * 0.0625f;
    const float bw = (x2 - x1) * (1.f / 7.f);
    const float bh = (y2 - y1) * (1.f / 7.f);

    float best = -1e30f;
#pragma unroll
    for (int sy = 0; sy < 2; ++sy) {
        float ys = y1 + ((float)gh + (sy + 0.5f) * 0.5f) * bh;
        ys = fminf(fmaxf(ys, 0.f), (float)(H_SP - 1));
        const float y0f = floorf(ys);
        const float ly  = ys - y0f;
        const int iy0 = (int)y0f;
        const int iy1 = min(iy0 + 1, H_SP - 1);
#pragma unroll
        for (int sx = 0; sx < 2; ++sx) {
            float xs = x1 + ((float)gw + (sx + 0.5f) * 0.5f) * bw;
            xs = fminf(fmaxf(xs, 0.f), (float)(W_SP - 1));
            const float x0f = floorf(xs);
            const float lx  = xs - x0f;
            const int ix0 = (int)x0f;
            const int ix1 = min(ix0 + 1, W_SP - 1);
            const float v00 = hT[(size_t)(iy0 * W_SP + ix0) * C_MID + c];
            const float v01 = hT[(size_t)(iy0 * W_SP + ix1) * C_MID + c];
            const float v10 = hT[(size_t)(iy1 * W_SP + ix0) * C_MID + c];
            const float v11 = hT[(size_t)(iy1 * W_SP + ix1) * C_MID + c];
            const float v = (1.f - ly) * ((1.f - lx) * v00 + lx * v01)
                          + ly        * ((1.f - lx) * v10 + lx * v11);
            best = fmaxf(best, v);
        }
    }
    out[idx] = best;
}

// ---------------------------------------------------------------------------
// Generic NT GEMM (FC layers)
// ---------------------------------------------------------------------------
template<bool RELU>
__global__ __launch_bounds__(256) void gemm_nt(
    const float* __restrict__ A, const float* __restrict__ B,
    const float* __restrict__ bias, float* __restrict__ C,
    int M, int N, int K, int ldc)
{
    __shared__ float As[16][64];
    __shared__ float Bs[16][64];

    const int nBase = blockIdx.x * 64;
    const int mBase = blockIdx.y * 64;
    const int t  = threadIdx.x;
    const int tx = t & 15;
    const int ty = t >> 4;
    const int lr = t >> 2;
    const int lk = (t & 3) * 4;

    float acc[4][4];
#pragma unroll
    for (int i = 0; i < 4; ++i)
#pragma unroll
        for (int j = 0; j < 4; ++j) acc[i][j] = 0.f;

    const bool aok = (mBase + lr) < M;
    const bool bok = (nBase + lr) < N;
    const float* Arow = A + (size_t)(aok ? (mBase + lr) : 0) * K;
    const float* Brow = B + (size_t)(bok ? (nBase + lr) : 0) * K;

    for (int k0 = 0; k0 < K; k0 += 16) {
#pragma unroll
        for (int i = 0; i < 4; ++i) {
            const int kk = k0 + lk + i;
            const bool kin = kk < K;
            As[lk + i][lr] = (aok && kin) ? Arow[kk] : 0.f;
            Bs[lk + i][lr] = (bok && kin) ? Brow[kk] : 0.f;
        }
        __syncthreads();
#pragma unroll
        for (int k = 0; k < 16; ++k) {
            const float4 a4 = *(const float4*)&As[k][ty * 4];
            const float4 b4 = *(const float4*)&Bs[k][tx * 4];
            const float ar[4] = {a4.x, a4.y, a4.z, a4.w};
            const float br[4] = {b4.x, b4.y, b4.z, b4.w};
#pragma unroll
            for (int i = 0; i < 4; ++i)
#pragma unroll
                for (int j = 0; j < 4; ++j)
                    acc[i][j] = fmaf(ar[i], br[j], acc[i][j]);
        }
        __syncthreads();
    }

#pragma unroll
    for (int i = 0; i < 4; ++i) {
        const int m = mBase + ty * 4 + i;
        if (m >= M) continue;
#pragma unroll
        for (int j = 0; j < 4; ++j) {
            const int n = nBase + tx * 4 + j;
            if (n >= N) continue;
            float v = acc[i][j] + bias[n];
            if (RELU) v = fmaxf(v, 0.f);
            C[(size_t)m * ldc + n] = v;
        }
    }
}

// ---------------------------------------------------------------------------
// Launch
// ---------------------------------------------------------------------------
extern "C" void kernel_launch(void* const* d_in, const int* in_sizes, int n_in,
                              void* d_out, int out_size)
{
    const float* x         = (const float*)d_in[0];
    const float* rois      = (const float*)d_in[1];
    const float* w_col_max = (const float*)d_in[2];
    const float* b_col_max = (const float*)d_in[3];
    const float* w_col     = (const float*)d_in[4];
    const float* b_col     = (const float*)d_in[5];
    const float* w_row_max = (const float*)d_in[6];
    const float* b_row_max = (const float*)d_in[7];
    const float* w_row     = (const float*)d_in[8];
    const float* b_row     = (const float*)d_in[9];
    const float* fc1_w     = (const float*)d_in[10];
    const float* fc1_b     = (const float*)d_in[11];
    const float* score_w   = (const float*)d_in[12];
    const float* score_b   = (const float*)d_in[13];
    const float* loc_w     = (const float*)d_in[14];
    const float* loc_b     = (const float*)d_in[15];
    float* out = (float*)d_out;

    __nv_bfloat16 *w1hi, *w1lo, *w2hi, *w2lo, *xthi, *xtlo, *y1thi, *y1tlo;
    float *hT, *flat, *fc1;
    cudaGetSymbolAddress((void**)&w1hi,  g_w1hi);
    cudaGetSymbolAddress((void**)&w1lo,  g_w1lo);
    cudaGetSymbolAddress((void**)&w2hi,  g_w2hi);
    cudaGetSymbolAddress((void**)&w2lo,  g_w2lo);
    cudaGetSymbolAddress((void**)&xthi,  g_xthi);
    cudaGetSymbolAddress((void**)&xtlo,  g_xtlo);
    cudaGetSymbolAddress((void**)&y1thi, g_y1thi);
    cudaGetSymbolAddress((void**)&y1tlo, g_y1tlo);
    cudaGetSymbolAddress((void**)&hT,    g_hT);
    cudaGetSymbolAddress((void**)&flat,  g_flat);
    cudaGetSymbolAddress((void**)&fc1,   g_fc1);

    cudaFuncSetAttribute(conv_mma<1>, cudaFuncAttributeMaxDynamicSharedMemorySize, DYN_SMEM);
    cudaFuncSetAttribute(conv_mma<2>, cudaFuncAttributeMaxDynamicSharedMemorySize, DYN_SMEM);

    // Prep: weight/activation layout + bf16 hi/lo split
    prep_w1<<<512, 256>>>(w_col_max, w_row_max, w1hi, w1lo);
    prep_w2<<<dim3(490, 2), 256>>>(w_col, w_row, w2hi, w2lo);
    prep_xt<<<dim3(118, 64), 256>>>(x, xthi, xtlo);

    // conv1 (both 2048->256 branches, M=512): 30 x 4 tiles = 120 CTAs
    conv_mma<1><<<dim3(30, 4), 256, DYN_SMEM>>>(
        w1hi, w1lo, xthi, xtlo, b_col_max, b_row_max, y1thi, y1tlo, nullptr);

    // conv2 (sum of both 256->490 branches + relu): 30 x 4 tiles
    conv_mma<2><<<dim3(30, 4), 256, DYN_SMEM>>>(
        w2hi, w2lo, y1thi, y1tlo, b_col, b_row, nullptr, nullptr, hT);

    // PSROI align max -> flat [1000, 490]
    psroi_kernel<<<(R_ROIS * C_MID + 255) / 256, 256>>>(hT, rois, flat);

    // fc1 = relu(flat @ fc1_w^T + b) -> [1000, 2048]
    gemm_nt<true ><<<dim3(FC1_DIM / 64, (R_ROIS + 63) / 64), 256>>>(
        flat, fc1_w, fc1_b, fc1, R_ROIS, FC1_DIM, C_MID, FC1_DIM);

    // heads: locs (out[0:324000]) then scores (out[324000:405000])
    gemm_nt<false><<<dim3((LOC_DIM + 63) / 64, (R_ROIS + 63) / 64), 256>>>(
        fc1, loc_w, loc_b, out, R_ROIS, LOC_DIM, FC1_DIM, LOC_DIM);
    gemm_nt<false><<<dim3((SCORE_DIM + 63) / 64, (R_ROIS + 63) / 64), 256>>>(
        fc1, score_w, score_b, out + (size_t)R_ROIS * LOC_DIM,
        R_ROIS, SCORE_DIM, FC1_DIM, SCORE_DIM);
}